// round 2
// baseline (speedup 1.0000x reference)
#include <cuda_runtime.h>
#include <cstdint>

// Problem constants (fixed by setup_inputs)
#define NN 200000      // nodes
#define NE 800000      // edges (divisible by 64)
#define HH 128         // hidden
#define NG 8000        // graphs
#define AF 39          // atom feature dim
#define BF 11          // bond feature dim
#define KI 50          // AF+BF
#define KO 167         // AF+HH
#define KOP 168        // padded KO
#define DEPTH 6

// ---------------- scratch (device globals; no allocations allowed) ----------
__device__ float g_msg_input[(size_t)NE * HH];   // pre-relu W_i output
__device__ float g_Z0[(size_t)NE * HH];
__device__ float g_Z1[(size_t)NE * HH];
__device__ float g_nZ0[(size_t)NN * HH];
__device__ float g_nZ1[(size_t)NN * HH];
__device__ float g_m[(size_t)NN * HH];
__device__ float g_inv[NG];
__device__ int   g_cnt[NG];

// ---------------- packed f32x2 helpers (sm_100+) ----------------------------
__device__ __forceinline__ unsigned long long pk2(float a, float b) {
    unsigned long long r;
    asm("mov.b64 %0, {%1, %2};" : "=l"(r)
        : "r"(__float_as_uint(a)), "r"(__float_as_uint(b)));
    return r;
}
__device__ __forceinline__ void fma2(unsigned long long& d,
                                     unsigned long long a,
                                     unsigned long long b) {
    asm("fma.rn.f32x2 %0, %1, %2, %0;" : "+l"(d) : "l"(a), "l"(b));
}
__device__ __forceinline__ float lo2(unsigned long long p) {
    return __uint_as_float((unsigned)(p & 0xffffffffull));
}
__device__ __forceinline__ float hi2(unsigned long long p) {
    return __uint_as_float((unsigned)(p >> 32));
}

// ---------------- small kernels ---------------------------------------------
__global__ void count_k(const int* __restrict__ gid, int* __restrict__ cnt) {
    int v = blockIdx.x * 256 + threadIdx.x;
    if (v < NN) atomicAdd(&cnt[gid[v]], 1);
}
__global__ void inv_k(const int* __restrict__ cnt, float* __restrict__ inv) {
    int g = blockIdx.x * 256 + threadIdx.x;
    if (g < NG) inv[g] = 1.0f / fmaxf((float)cnt[g], 1.0f);
}

// ---------------- msg_input = cat(atom_x[src], bond_x) @ W_i^T ---------------
// 64 edges/block, 256 threads; register tile 8 edges x 4 outputs (2x f32x2).
// k vectorized by 2 (float2 msg loads).
__global__ __launch_bounds__(256) void mk_msg_input(
    const float* __restrict__ atom_x, const float* __restrict__ bond_x,
    const int* __restrict__ src, const float* __restrict__ Wi,
    float* __restrict__ msg_input)
{
    __shared__ float wt[KI * HH];        // wt[k*128 + j] = Wi[j*50 + k]
    __shared__ float fs[64 * KI];        // fs[le*50 + k]
    __shared__ int s_src[64];

    int tid = threadIdx.x;
    int base = blockIdx.x * 64;

    if (tid < 64) s_src[tid] = src[base + tid];
    __syncthreads();

    for (int idx = tid; idx < HH * KI; idx += 256) {
        int j = idx / KI, k = idx - j * KI;
        wt[k * HH + j] = Wi[idx];
    }
    for (int idx = tid; idx < 64 * KI; idx += 256) {
        int le = idx / KI, k = idx - le * KI;
        int e = base + le;
        float v = (k < AF) ? atom_x[(size_t)s_src[le] * AF + k]
                           : bond_x[(size_t)e * BF + (k - AF)];
        fs[idx] = v;
    }
    __syncthreads();

    int lane = tid & 31, wrp = tid >> 5;
    int e0 = wrp * 8;
    unsigned long long acc[8][2];
#pragma unroll
    for (int i = 0; i < 8; i++) { acc[i][0] = 0ull; acc[i][1] = 0ull; }

#pragma unroll 1
    for (int k = 0; k < KI; k += 2) {
        float2 m[8];
#pragma unroll
        for (int i = 0; i < 8; i++)
            m[i] = *reinterpret_cast<const float2*>(fs + (e0 + i) * KI + k);
#pragma unroll
        for (int kk = 0; kk < 2; kk++) {
            float4 w = *reinterpret_cast<const float4*>(wt + (k + kk) * HH + lane * 4);
            unsigned long long w01 = pk2(w.x, w.y), w23 = pk2(w.z, w.w);
#pragma unroll
            for (int i = 0; i < 8; i++) {
                float mv = kk ? m[i].y : m[i].x;
                unsigned long long m2 = pk2(mv, mv);
                fma2(acc[i][0], m2, w01);
                fma2(acc[i][1], m2, w23);
            }
        }
    }
#pragma unroll
    for (int i = 0; i < 8; i++) {
        int e = base + e0 + i;
        float4 z = make_float4(lo2(acc[i][0]), hi2(acc[i][0]),
                               lo2(acc[i][1]), hi2(acc[i][1]));
        reinterpret_cast<float4*>(msg_input)[(size_t)e * 32 + lane] = z;
    }
}

// ---------------- fused BP step ----------------------------------------------
// msg = relu(msg_input + nodeZprev[src] - Zprev[e^1])  (or relu(msg_input) if first)
// Zout = msg @ W_h^T ; nodeZout[dst] += Zout
#define FUSED_SMEM ((64 * HH + HH * 132) * 4)
__global__ __launch_bounds__(256) void fused_step(
    const float* __restrict__ msg_input,
    const float* __restrict__ Zprev, const float* __restrict__ nodeZprev,
    float* __restrict__ Zout, float* __restrict__ nodeZout,
    const float* __restrict__ Wh,
    const int* __restrict__ src, const int* __restrict__ dst, int first)
{
    extern __shared__ float sm[];
    float* m_s = sm;                 // 64*128
    float* wt  = sm + 64 * HH;       // 128*132 (padded for float4 + bank spread)
    __shared__ int s_src[64], s_dst[64];

    int tid = threadIdx.x;
    int base = blockIdx.x * 64;

    if (tid < 64) { s_src[tid] = src[base + tid]; s_dst[tid] = dst[base + tid]; }
    __syncthreads();

    // transposed W_h: wt[k*132 + j] = Wh[j*128 + k]
    for (int idx = tid; idx < HH * HH; idx += 256) {
        int j = idx >> 7, k = idx & 127;
        wt[k * 132 + j] = Wh[idx];
    }

    // phase A: build msg tile in smem
    const float4* mi4 = reinterpret_cast<const float4*>(msg_input);
    const float4* nz4 = reinterpret_cast<const float4*>(nodeZprev);
    const float4* zp4 = reinterpret_cast<const float4*>(Zprev);
    for (int idx = tid; idx < 64 * 32; idx += 256) {
        int le = idx >> 5, q = idx & 31;
        int e = base + le;
        float4 v = mi4[(size_t)e * 32 + q];
        if (!first) {
            float4 a = nz4[(size_t)s_src[le] * 32 + q];
            float4 b = zp4[(size_t)(e ^ 1) * 32 + q];
            v.x += a.x - b.x; v.y += a.y - b.y;
            v.z += a.z - b.z; v.w += a.w - b.w;
        }
        float4 r = make_float4(fmaxf(v.x, 0.f), fmaxf(v.y, 0.f),
                               fmaxf(v.z, 0.f), fmaxf(v.w, 0.f));
        reinterpret_cast<float4*>(m_s)[idx] = r;
    }
    __syncthreads();

    // phase B: GEMM 64x128 @ 128x128 with f32x2 FFMA, k vectorized by 4
    int lane = tid & 31, wrp = tid >> 5;
    int e0 = wrp * 8;
    unsigned long long acc[8][2];
#pragma unroll
    for (int i = 0; i < 8; i++) { acc[i][0] = 0ull; acc[i][1] = 0ull; }

#pragma unroll 1
    for (int k = 0; k < HH; k += 4) {
        float4 m[8];
#pragma unroll
        for (int i = 0; i < 8; i++)
            m[i] = *reinterpret_cast<const float4*>(m_s + (e0 + i) * HH + k);
#pragma unroll
        for (int kk = 0; kk < 4; kk++) {
            float4 w = *reinterpret_cast<const float4*>(wt + (k + kk) * 132 + lane * 4);
            unsigned long long w01 = pk2(w.x, w.y), w23 = pk2(w.z, w.w);
#pragma unroll
            for (int i = 0; i < 8; i++) {
                float mv = (kk == 0) ? m[i].x : (kk == 1) ? m[i].y
                         : (kk == 2) ? m[i].z : m[i].w;
                unsigned long long m2 = pk2(mv, mv);
                fma2(acc[i][0], m2, w01);
                fma2(acc[i][1], m2, w23);
            }
        }
    }

    // epilogue: store Z, scatter into nodeZ with vector atomics
#pragma unroll
    for (int i = 0; i < 8; i++) {
        int le = e0 + i;
        int e = base + le;
        float4 z = make_float4(lo2(acc[i][0]), hi2(acc[i][0]),
                               lo2(acc[i][1]), hi2(acc[i][1]));
        reinterpret_cast<float4*>(Zout)[(size_t)e * 32 + lane] = z;
        atomicAdd(reinterpret_cast<float4*>(nodeZout + (size_t)s_dst[le] * HH + lane * 4), z);
    }
}

// ---------------- final msg + node aggregation -------------------------------
__global__ void final_msg(
    const float* __restrict__ msg_input,
    const float* __restrict__ Z, const float* __restrict__ nodeZ,
    const int* __restrict__ src, const int* __restrict__ dst,
    float* __restrict__ m)
{
    int idx = blockIdx.x * 256 + threadIdx.x;   // over NE*32 float4s
    int e = idx >> 5, q = idx & 31;
    float4 v = reinterpret_cast<const float4*>(msg_input)[(size_t)e * 32 + q];
    float4 a = reinterpret_cast<const float4*>(nodeZ)[(size_t)__ldg(src + e) * 32 + q];
    float4 b = reinterpret_cast<const float4*>(Z)[(size_t)(e ^ 1) * 32 + q];
    float4 r = make_float4(fmaxf(v.x + a.x - b.x, 0.f),
                           fmaxf(v.y + a.y - b.y, 0.f),
                           fmaxf(v.z + a.z - b.z, 0.f),
                           fmaxf(v.w + a.w - b.w, 0.f));
    atomicAdd(reinterpret_cast<float4*>(m + (size_t)__ldg(dst + e) * HH + q * 4), r);
}

// ---------------- readout: h = relu(cat(atom_x, m) @ W_o^T + b_o); graph mean
// k padded to 168 (zero-filled), vectorized by 4.
#define NODE_SMEM ((KOP * HH + 64 * KOP) * 4)
__global__ __launch_bounds__(256) void node_out(
    const float* __restrict__ atom_x, const float* __restrict__ m,
    const int* __restrict__ gids, const float* __restrict__ Wo,
    const float* __restrict__ b_o, const float* __restrict__ inv,
    float* __restrict__ out)
{
    extern __shared__ float sm[];
    float* wt = sm;                  // KOP*128: wt[k*128+j] = Wo[j*167+k], row 167 = 0
    float* fs = sm + KOP * HH;       // 64*168, col 167 = 0
    __shared__ int s_gid[64];
    __shared__ float s_inv[64];

    int tid = threadIdx.x;
    int base = blockIdx.x * 64;

    if (tid < 64) {
        int g = gids[base + tid];
        s_gid[tid] = g;
        s_inv[tid] = inv[g];
    }

    for (int idx = tid; idx < HH * KOP; idx += 256) {
        int j = idx / KOP, k = idx - j * KOP;
        wt[k * HH + j] = (k < KO) ? Wo[(size_t)j * KO + k] : 0.f;
    }
    for (int idx = tid; idx < 64 * KOP; idx += 256) {
        int le = idx / KOP, k = idx - le * KOP;
        int v = base + le;
        float val;
        if (k < AF)        val = atom_x[(size_t)v * AF + k];
        else if (k < KO)   val = m[(size_t)v * HH + (k - AF)];
        else               val = 0.f;
        fs[idx] = val;
    }
    __syncthreads();

    int lane = tid & 31, wrp = tid >> 5;
    int n0 = wrp * 8;
    unsigned long long acc[8][2];
#pragma unroll
    for (int i = 0; i < 8; i++) { acc[i][0] = 0ull; acc[i][1] = 0ull; }

#pragma unroll 1
    for (int k = 0; k < KOP; k += 4) {
        float4 mf[8];
#pragma unroll
        for (int i = 0; i < 8; i++)
            mf[i] = *reinterpret_cast<const float4*>(fs + (n0 + i) * KOP + k);
#pragma unroll
        for (int kk = 0; kk < 4; kk++) {
            float4 w = *reinterpret_cast<const float4*>(wt + (k + kk) * HH + lane * 4);
            unsigned long long w01 = pk2(w.x, w.y), w23 = pk2(w.z, w.w);
#pragma unroll
            for (int i = 0; i < 8; i++) {
                float mv = (kk == 0) ? mf[i].x : (kk == 1) ? mf[i].y
                         : (kk == 2) ? mf[i].z : mf[i].w;
                unsigned long long m2 = pk2(mv, mv);
                fma2(acc[i][0], m2, w01);
                fma2(acc[i][1], m2, w23);
            }
        }
    }

    float4 b = *reinterpret_cast<const float4*>(b_o + lane * 4);
#pragma unroll
    for (int i = 0; i < 8; i++) {
        int le = n0 + i;
        float iv = s_inv[le];
        float4 h = make_float4(fmaxf(lo2(acc[i][0]) + b.x, 0.f) * iv,
                               fmaxf(hi2(acc[i][0]) + b.y, 0.f) * iv,
                               fmaxf(lo2(acc[i][1]) + b.z, 0.f) * iv,
                               fmaxf(hi2(acc[i][1]) + b.w, 0.f) * iv);
        atomicAdd(reinterpret_cast<float4*>(out + (size_t)s_gid[le] * HH + lane * 4), h);
    }
}

// ---------------- launch -----------------------------------------------------
extern "C" void kernel_launch(void* const* d_in, const int* in_sizes, int n_in,
                              void* d_out, int out_size) {
    const float* atom_x = (const float*)d_in[0];
    const float* bond_x = (const float*)d_in[1];
    const int*   src    = (const int*)d_in[2];
    const int*   dst    = (const int*)d_in[3];
    const int*   gids   = (const int*)d_in[4];
    const float* W_i    = (const float*)d_in[5];
    const float* W_h    = (const float*)d_in[6];
    const float* W_o    = (const float*)d_in[7];
    const float* b_o    = (const float*)d_in[8];
    float* out = (float*)d_out;

    void *p_mi, *p_z0, *p_z1, *p_n0, *p_n1, *p_m, *p_inv, *p_cnt;
    cudaGetSymbolAddress(&p_mi, g_msg_input);
    cudaGetSymbolAddress(&p_z0, g_Z0);
    cudaGetSymbolAddress(&p_z1, g_Z1);
    cudaGetSymbolAddress(&p_n0, g_nZ0);
    cudaGetSymbolAddress(&p_n1, g_nZ1);
    cudaGetSymbolAddress(&p_m,  g_m);
    cudaGetSymbolAddress(&p_inv, g_inv);
    cudaGetSymbolAddress(&p_cnt, g_cnt);
    cudaFuncSetAttribute(fused_step, cudaFuncAttributeMaxDynamicSharedMemorySize, FUSED_SMEM);
    cudaFuncSetAttribute(node_out,   cudaFuncAttributeMaxDynamicSharedMemorySize, NODE_SMEM);

    cudaMemsetAsync(p_cnt, 0, NG * sizeof(int));
    cudaMemsetAsync(out, 0, (size_t)out_size * sizeof(float));

    count_k<<<(NN + 255) / 256, 256>>>(gids, (int*)p_cnt);
    inv_k<<<(NG + 255) / 256, 256>>>((const int*)p_cnt, (float*)p_inv);

    mk_msg_input<<<NE / 64, 256>>>(atom_x, bond_x, src, W_i, (float*)p_mi);

    float* Zb[2] = {(float*)p_z0, (float*)p_z1};
    float* Nb[2] = {(float*)p_n0, (float*)p_n1};
    for (int t = 0; t < DEPTH - 1; t++) {
        cudaMemsetAsync(Nb[t & 1], 0, (size_t)NN * HH * sizeof(float));
        fused_step<<<NE / 64, 256, FUSED_SMEM>>>(
            (const float*)p_mi, Zb[(t + 1) & 1], Nb[(t + 1) & 1],
            Zb[t & 1], Nb[t & 1], W_h, src, dst, t == 0);
    }
    int last = (DEPTH - 2) & 1;   // = 0 for depth 6

    cudaMemsetAsync(p_m, 0, (size_t)NN * HH * sizeof(float));
    final_msg<<<(NE * 32) / 256, 256>>>((const float*)p_mi, Zb[last], Nb[last],
                                        src, dst, (float*)p_m);

    node_out<<<NN / 64, 256, NODE_SMEM>>>(atom_x, (const float*)p_m, gids,
                                          W_o, b_o, (const float*)p_inv, out);
}

// round 3
// speedup vs baseline: 1.2057x; 1.2057x over previous
#include <cuda_runtime.h>
#include <cstdint>

// Problem constants (fixed by setup_inputs)
#define NN 200000      // nodes
#define NE 800000      // edges (divisible by 64)
#define HH 128         // hidden
#define NG 8000        // graphs
#define AF 39          // atom feature dim
#define BF 11          // bond feature dim
#define KI 50          // AF+BF
#define KO 167         // AF+HH
#define NT (NE / 64)   // 12500 edge tiles
#define DEPTH 6

// ---------------- scratch (device globals; no allocations allowed) ----------
__device__ float g_msg_input[(size_t)NE * HH];   // pre-relu W_i output
__device__ float g_Z0[(size_t)NE * HH];
__device__ float g_Z1[(size_t)NE * HH];
__device__ float g_nZ0[(size_t)NN * HH];
__device__ float g_nZ1[(size_t)NN * HH];
__device__ float g_m[(size_t)NN * HH];
__device__ float g_inv[NG];
__device__ int   g_cnt[NG];

// ---------------- packed f32x2 helpers (sm_100+) ----------------------------
__device__ __forceinline__ unsigned long long pk2(float a, float b) {
    unsigned long long r;
    asm("mov.b64 %0, {%1, %2};" : "=l"(r)
        : "r"(__float_as_uint(a)), "r"(__float_as_uint(b)));
    return r;
}
__device__ __forceinline__ void fma2(unsigned long long& d,
                                     unsigned long long a,
                                     unsigned long long b) {
    asm("fma.rn.f32x2 %0, %1, %2, %0;" : "+l"(d) : "l"(a), "l"(b));
}
__device__ __forceinline__ float lo2(unsigned long long p) {
    return __uint_as_float((unsigned)(p & 0xffffffffull));
}
__device__ __forceinline__ float hi2(unsigned long long p) {
    return __uint_as_float((unsigned)(p >> 32));
}

// ---------------- small kernels ---------------------------------------------
__global__ void count_k(const int* __restrict__ gid, int* __restrict__ cnt) {
    int v = blockIdx.x * 256 + threadIdx.x;
    if (v < NN) atomicAdd(&cnt[gid[v]], 1);
}
__global__ void inv_k(const int* __restrict__ cnt, float* __restrict__ inv) {
    int g = blockIdx.x * 256 + threadIdx.x;
    if (g < NG) inv[g] = 1.0f / fmaxf((float)cnt[g], 1.0f);
}

// ---------------- msg_input = cat(atom_x[src], bond_x) @ W_i^T ---------------
// (R0 version — 64 edges/block, 256 threads)
__global__ __launch_bounds__(256) void mk_msg_input(
    const float* __restrict__ atom_x, const float* __restrict__ bond_x,
    const int* __restrict__ src, const float* __restrict__ Wi,
    float* __restrict__ msg_input)
{
    __shared__ float wt[KI * HH];        // wt[k*128 + j] = Wi[j*50 + k]
    __shared__ float fs[64 * KI];        // fs[le*50 + k]
    __shared__ int s_src[64];

    int tid = threadIdx.x;
    int base = blockIdx.x * 64;

    if (tid < 64) s_src[tid] = src[base + tid];
    __syncthreads();

    for (int idx = tid; idx < HH * KI; idx += 256) {
        int j = idx / KI, k = idx - j * KI;
        wt[k * HH + j] = Wi[idx];
    }
    for (int idx = tid; idx < 64 * KI; idx += 256) {
        int le = idx / KI, k = idx - le * KI;
        int e = base + le;
        float v = (k < AF) ? atom_x[(size_t)s_src[le] * AF + k]
                           : bond_x[(size_t)e * BF + (k - AF)];
        fs[idx] = v;
    }
    __syncthreads();

    int lane = tid & 31, wrp = tid >> 5;
    int e0 = wrp * 8;
    unsigned long long acc[8][2];
#pragma unroll
    for (int i = 0; i < 8; i++) { acc[i][0] = 0ull; acc[i][1] = 0ull; }

    for (int k = 0; k < KI; k++) {
        float4 w = *reinterpret_cast<const float4*>(wt + k * HH + lane * 4);
        unsigned long long w01 = pk2(w.x, w.y), w23 = pk2(w.z, w.w);
#pragma unroll
        for (int i = 0; i < 8; i++) {
            float mv = fs[(e0 + i) * KI + k];
            unsigned long long m2 = pk2(mv, mv);
            fma2(acc[i][0], m2, w01);
            fma2(acc[i][1], m2, w23);
        }
    }
#pragma unroll
    for (int i = 0; i < 8; i++) {
        int e = base + e0 + i;
        float4 z = make_float4(lo2(acc[i][0]), hi2(acc[i][0]),
                               lo2(acc[i][1]), hi2(acc[i][1]));
        reinterpret_cast<float4*>(msg_input)[(size_t)e * 32 + lane] = z;
    }
}

// ---------------- fused BP step (persistent, barrier-free, pipelined) --------
// msg = relu(msg_input + nodeZprev[src] - Zprev[e^1])  (or relu(msg_input) if first)
// Zout = msg @ W_h^T ; nodeZout[dst] += Zout
//
// Each warp owns edge rows {wrp, wrp+8, ..., wrp+56} of the 64-edge tile:
// the msg smem rows are warp-private, so no __syncthreads in the tile loop.
// Next tile's global loads are prefetched into registers before the GEMM,
// so their ~600-cycle latency is hidden under 8192 cycles of FFMA2.
#define FUSED_SMEM ((HH * HH + 64 * HH) * 4)
__global__ __launch_bounds__(256, 1) void fused_step(
    const float* __restrict__ msg_input,
    const float* __restrict__ Zprev, const float* __restrict__ nodeZprev,
    float* __restrict__ Zout, float* __restrict__ nodeZout,
    const float* __restrict__ Wh,
    const int* __restrict__ src, const int* __restrict__ dst, int first)
{
    extern __shared__ float sm[];
    float* wt  = sm;             // 128*128: wt[k*128 + j] = Wh[j*128 + k]
    float* m_s = sm + HH * HH;   // 64*128 msg tile (warp-private rows)

    int tid  = threadIdx.x;
    int lane = tid & 31, wrp = tid >> 5;

    for (int idx = tid; idx < HH * HH; idx += 256) {
        int j = idx >> 7, k = idx & 127;
        wt[k * HH + j] = Wh[idx];
    }
    __syncthreads();   // the only barrier

    const float4* mi4 = reinterpret_cast<const float4*>(msg_input);
    const float4* nz4 = reinterpret_cast<const float4*>(nodeZprev);
    const float4* zp4 = reinterpret_cast<const float4*>(Zprev);

    const int S = gridDim.x;
    int t0 = blockIdx.x;
    if (t0 >= NT) return;

    float4 p_mi[8], p_nz[8], p_zp[8];
    int cur_d[8], nxt_d[8];

    // ---- prefetch + combine for first tile ----
#pragma unroll
    for (int j = 0; j < 8; j++) {
        int e = t0 * 64 + wrp + j * 8;
        nxt_d[j] = __ldg(dst + e);
        p_mi[j] = mi4[(size_t)e * 32 + lane];
        if (!first) {
            int s = __ldg(src + e);
            p_nz[j] = nz4[(size_t)s * 32 + lane];
            p_zp[j] = zp4[(size_t)(e ^ 1) * 32 + lane];
        }
    }
#pragma unroll
    for (int j = 0; j < 8; j++) {
        int le = wrp + j * 8;
        float4 v = p_mi[j];
        if (!first) {
            v.x += p_nz[j].x - p_zp[j].x; v.y += p_nz[j].y - p_zp[j].y;
            v.z += p_nz[j].z - p_zp[j].z; v.w += p_nz[j].w - p_zp[j].w;
        }
        float4 r = make_float4(fmaxf(v.x, 0.f), fmaxf(v.y, 0.f),
                               fmaxf(v.z, 0.f), fmaxf(v.w, 0.f));
        *reinterpret_cast<float4*>(m_s + le * HH + lane * 4) = r;
    }
#pragma unroll
    for (int j = 0; j < 8; j++) cur_d[j] = nxt_d[j];

    for (int t = t0; t < NT; t += S) {
        int tn = t + S;
        bool hn = tn < NT;

        // ---- prefetch next tile (latency hidden under the GEMM below) ----
        if (hn) {
#pragma unroll
            for (int j = 0; j < 8; j++) {
                int e = tn * 64 + wrp + j * 8;
                nxt_d[j] = __ldg(dst + e);
                p_mi[j] = mi4[(size_t)e * 32 + lane];
                if (!first) {
                    int s = __ldg(src + e);
                    p_nz[j] = nz4[(size_t)s * 32 + lane];
                    p_zp[j] = zp4[(size_t)(e ^ 1) * 32 + lane];
                }
            }
        }

        // ---- GEMM 8 rows x 128 cols, k vectorized by 4 ----
        unsigned long long acc[8][2];
#pragma unroll
        for (int i = 0; i < 8; i++) { acc[i][0] = 0ull; acc[i][1] = 0ull; }

#pragma unroll 1
        for (int k = 0; k < HH; k += 4) {
            float4 m[8];
#pragma unroll
            for (int i = 0; i < 8; i++)
                m[i] = *reinterpret_cast<const float4*>(m_s + (wrp + i * 8) * HH + k);
#pragma unroll
            for (int kk = 0; kk < 4; kk++) {
                float4 w = *reinterpret_cast<const float4*>(wt + (k + kk) * HH + lane * 4);
                unsigned long long w01 = pk2(w.x, w.y), w23 = pk2(w.z, w.w);
#pragma unroll
                for (int i = 0; i < 8; i++) {
                    float mv = (kk == 0) ? m[i].x : (kk == 1) ? m[i].y
                             : (kk == 2) ? m[i].z : m[i].w;
                    unsigned long long m2 = pk2(mv, mv);
                    fma2(acc[i][0], m2, w01);
                    fma2(acc[i][1], m2, w23);
                }
            }
        }

        // ---- epilogue: store Z, scatter-add into nodeZ ----
#pragma unroll
        for (int j = 0; j < 8; j++) {
            int e = t * 64 + wrp + j * 8;
            float4 z = make_float4(lo2(acc[j][0]), hi2(acc[j][0]),
                                   lo2(acc[j][1]), hi2(acc[j][1]));
            reinterpret_cast<float4*>(Zout)[(size_t)e * 32 + lane] = z;
            atomicAdd(reinterpret_cast<float4*>(
                nodeZout + (size_t)cur_d[j] * HH + lane * 4), z);
        }

        // ---- combine next tile into (warp-private) smem rows ----
        if (hn) {
#pragma unroll
            for (int j = 0; j < 8; j++) {
                int le = wrp + j * 8;
                float4 v = p_mi[j];
                if (!first) {
                    v.x += p_nz[j].x - p_zp[j].x; v.y += p_nz[j].y - p_zp[j].y;
                    v.z += p_nz[j].z - p_zp[j].z; v.w += p_nz[j].w - p_zp[j].w;
                }
                float4 r = make_float4(fmaxf(v.x, 0.f), fmaxf(v.y, 0.f),
                                       fmaxf(v.z, 0.f), fmaxf(v.w, 0.f));
                *reinterpret_cast<float4*>(m_s + le * HH + lane * 4) = r;
            }
#pragma unroll
            for (int j = 0; j < 8; j++) cur_d[j] = nxt_d[j];
        }
    }
}

// ---------------- final msg + node aggregation -------------------------------
__global__ void final_msg(
    const float* __restrict__ msg_input,
    const float* __restrict__ Z, const float* __restrict__ nodeZ,
    const int* __restrict__ src, const int* __restrict__ dst,
    float* __restrict__ m)
{
    int idx = blockIdx.x * 256 + threadIdx.x;   // over NE*32 float4s
    int e = idx >> 5, q = idx & 31;
    float4 v = reinterpret_cast<const float4*>(msg_input)[(size_t)e * 32 + q];
    float4 a = reinterpret_cast<const float4*>(nodeZ)[(size_t)__ldg(src + e) * 32 + q];
    float4 b = reinterpret_cast<const float4*>(Z)[(size_t)(e ^ 1) * 32 + q];
    float4 r = make_float4(fmaxf(v.x + a.x - b.x, 0.f),
                           fmaxf(v.y + a.y - b.y, 0.f),
                           fmaxf(v.z + a.z - b.z, 0.f),
                           fmaxf(v.w + a.w - b.w, 0.f));
    atomicAdd(reinterpret_cast<float4*>(m + (size_t)__ldg(dst + e) * HH + q * 4), r);
}

// ---------------- readout: h = relu(cat(atom_x, m) @ W_o^T + b_o); graph mean
// (R0 version)
#define NODE_SMEM ((KO * HH + 64 * KO) * 4)
__global__ __launch_bounds__(256) void node_out(
    const float* __restrict__ atom_x, const float* __restrict__ m,
    const int* __restrict__ gids, const float* __restrict__ Wo,
    const float* __restrict__ b_o, const float* __restrict__ inv,
    float* __restrict__ out)
{
    extern __shared__ float sm[];
    float* wt = sm;                  // KO*128: wt[k*128+j] = Wo[j*167+k]
    float* fs = sm + KO * HH;        // 64*167
    __shared__ int s_gid[64];
    __shared__ float s_inv[64];

    int tid = threadIdx.x;
    int base = blockIdx.x * 64;

    if (tid < 64) {
        int g = gids[base + tid];
        s_gid[tid] = g;
        s_inv[tid] = inv[g];
    }

    for (int idx = tid; idx < HH * KO; idx += 256) {
        int j = idx / KO, k = idx - j * KO;
        wt[k * HH + j] = Wo[idx];
    }
    for (int idx = tid; idx < 64 * KO; idx += 256) {
        int le = idx / KO, k = idx - le * KO;
        int v = base + le;
        float val = (k < AF) ? atom_x[(size_t)v * AF + k]
                             : m[(size_t)v * HH + (k - AF)];
        fs[idx] = val;
    }
    __syncthreads();

    int lane = tid & 31, wrp = tid >> 5;
    int n0 = wrp * 8;
    unsigned long long acc[8][2];
#pragma unroll
    for (int i = 0; i < 8; i++) { acc[i][0] = 0ull; acc[i][1] = 0ull; }

    for (int k = 0; k < KO; k++) {
        float4 w = *reinterpret_cast<const float4*>(wt + k * HH + lane * 4);
        unsigned long long w01 = pk2(w.x, w.y), w23 = pk2(w.z, w.w);
#pragma unroll
        for (int i = 0; i < 8; i++) {
            float mv = fs[(n0 + i) * KO + k];
            unsigned long long m2 = pk2(mv, mv);
            fma2(acc[i][0], m2, w01);
            fma2(acc[i][1], m2, w23);
        }
    }

    float4 b = *reinterpret_cast<const float4*>(b_o + lane * 4);
#pragma unroll
    for (int i = 0; i < 8; i++) {
        int le = n0 + i;
        float iv = s_inv[le];
        float4 h = make_float4(fmaxf(lo2(acc[i][0]) + b.x, 0.f) * iv,
                               fmaxf(hi2(acc[i][0]) + b.y, 0.f) * iv,
                               fmaxf(lo2(acc[i][1]) + b.z, 0.f) * iv,
                               fmaxf(hi2(acc[i][1]) + b.w, 0.f) * iv);
        atomicAdd(reinterpret_cast<float4*>(out + (size_t)s_gid[le] * HH + lane * 4), h);
    }
}

// ---------------- launch -----------------------------------------------------
extern "C" void kernel_launch(void* const* d_in, const int* in_sizes, int n_in,
                              void* d_out, int out_size) {
    const float* atom_x = (const float*)d_in[0];
    const float* bond_x = (const float*)d_in[1];
    const int*   src    = (const int*)d_in[2];
    const int*   dst    = (const int*)d_in[3];
    const int*   gids   = (const int*)d_in[4];
    const float* W_i    = (const float*)d_in[5];
    const float* W_h    = (const float*)d_in[6];
    const float* W_o    = (const float*)d_in[7];
    const float* b_o    = (const float*)d_in[8];
    float* out = (float*)d_out;

    void *p_mi, *p_z0, *p_z1, *p_n0, *p_n1, *p_m, *p_inv, *p_cnt;
    cudaGetSymbolAddress(&p_mi, g_msg_input);
    cudaGetSymbolAddress(&p_z0, g_Z0);
    cudaGetSymbolAddress(&p_z1, g_Z1);
    cudaGetSymbolAddress(&p_n0, g_nZ0);
    cudaGetSymbolAddress(&p_n1, g_nZ1);
    cudaGetSymbolAddress(&p_m,  g_m);
    cudaGetSymbolAddress(&p_inv, g_inv);
    cudaGetSymbolAddress(&p_cnt, g_cnt);
    cudaFuncSetAttribute(fused_step, cudaFuncAttributeMaxDynamicSharedMemorySize, FUSED_SMEM);
    cudaFuncSetAttribute(node_out,   cudaFuncAttributeMaxDynamicSharedMemorySize, NODE_SMEM);

    cudaMemsetAsync(p_cnt, 0, NG * sizeof(int));
    cudaMemsetAsync(out, 0, (size_t)out_size * sizeof(float));

    count_k<<<(NN + 255) / 256, 256>>>(gids, (int*)p_cnt);
    inv_k<<<(NG + 255) / 256, 256>>>((const int*)p_cnt, (float*)p_inv);

    mk_msg_input<<<NE / 64, 256>>>(atom_x, bond_x, src, W_i, (float*)p_mi);

    float* Zb[2] = {(float*)p_z0, (float*)p_z1};
    float* Nb[2] = {(float*)p_n0, (float*)p_n1};
    for (int t = 0; t < DEPTH - 1; t++) {
        cudaMemsetAsync(Nb[t & 1], 0, (size_t)NN * HH * sizeof(float));
        fused_step<<<296, 256, FUSED_SMEM>>>(
            (const float*)p_mi, Zb[(t + 1) & 1], Nb[(t + 1) & 1],
            Zb[t & 1], Nb[t & 1], W_h, src, dst, t == 0);
    }
    int last = (DEPTH - 2) & 1;   // = 0 for depth 6

    cudaMemsetAsync(p_m, 0, (size_t)NN * HH * sizeof(float));
    final_msg<<<(NE * 32) / 256, 256>>>((const float*)p_mi, Zb[last], Nb[last],
                                        src, dst, (float*)p_m);

    node_out<<<NN / 64, 256, NODE_SMEM>>>(atom_x, (const float*)p_m, gids,
                                          W_o, b_o, (const float*)p_inv, out);
}